// round 16
// baseline (speedup 1.0000x reference)
#include <cuda_runtime.h>
#include <cstdint>

// Problem: out[b,s,e] = sum_v in[b,v,s] * emb[v,e];  B=128, V=2048, S=1024, E=64
#define B_  128
#define V_  2048
#define S_  1024
#define E_  64

#define NK8  (V_ / 8)    // 256 k8 steps

__device__ __forceinline__ float tf32_rn(float x) {
    uint32_t u;
    asm("cvt.rna.tf32.f32 %0, %1;" : "=r"(u) : "f"(x));
    return __uint_as_float(u);
}

#define MMA_TF32(d, a, b)                                                     \
    asm volatile(                                                             \
        "mma.sync.aligned.m16n8k8.row.col.f32.tf32.tf32.f32 "                 \
        "{%0,%1,%2,%3},{%4,%5,%6,%7},{%8,%9},{%0,%1,%2,%3};"                  \
        : "+f"((d)[0]), "+f"((d)[1]), "+f"((d)[2]), "+f"((d)[3])              \
        : "r"((a)[0]), "r"((a)[1]), "r"((a)[2]), "r"((a)[3]),                 \
          "r"((b)[0]), "r"((b)[1]))

// ---- Precomputed B operand: emb in fragment order, tf32-RN converted ----
// g_P[(k8*8 + nt)*32 + lane] = { tf32(emb[k8*8+tg][nt*8+g]), tf32(emb[k8*8+tg+4][nt*8+g]) }
// with tg = lane&3, g = lane>>2.  Size: 256*8*32 float2 = 512 KB (L2-resident).
__device__ float2 g_P[NK8 * 8 * 32];

__global__ void embP_prep_kernel(const float* __restrict__ emb) {
    int t = blockIdx.x * 256 + threadIdx.x;   // 0 .. 65535
    int lane = t & 31;
    int nt   = (t >> 5) & 7;
    int k8   = t >> 8;
    int tg = lane & 3, g = lane >> 2;
    int n = nt * 8 + g;
    float2 v;
    v.x = tf32_rn(emb[(k8 * 8 + tg    ) * E_ + n]);
    v.y = tf32_rn(emb[(k8 * 8 + tg + 4) * E_ + n]);
    g_P[t] = v;
}

// ---- Main kernel: NO smem, NO barriers. ----
// CTA: 128 threads (4 warps). Warp tile 32(m=s) x 64(n=e); CTA m-tile 128.
// A fragments LDG'd directly from gmem (each element used exactly once chip-wide);
// B fragments LDG'd from fragment-ordered g_P (hot in L2/L1).
// A: 4-buffer ring, prefetch distance 2 (covers DRAM latency).
// B: 2-buffer ring, prefetch distance 1 (L2 hit latency).
__global__ __launch_bounds__(128, 3)
void Embedding_59476707115122_kernel(const float* __restrict__ in,
                                     float* __restrict__ out) {
    const int tid  = threadIdx.x;
    const int lane = tid & 31;
    const int wid  = tid >> 5;          // warp m-slice: [wid*32, +32)
    const int g  = lane >> 2;
    const int tg = lane & 3;

    const int sBase = blockIdx.x * 128;
    const int b     = blockIdx.y;
    // warp's A base: row k has stride S_, m offset = sBase + wid*32
    const float* inW  = in  + (size_t)b * ((size_t)V_ * S_) + sBase + wid * 32;
    float*       outB = out + (size_t)b * ((size_t)S_ * E_) + (size_t)sBase * E_;

    float acc[2][8][4];
    #pragma unroll
    for (int mt = 0; mt < 2; mt++)
        #pragma unroll
        for (int nt = 0; nt < 8; nt++)
            #pragma unroll
            for (int r = 0; r < 4; r++) acc[mt][nt][r] = 0.0f;

    // A fragment ring [4], B fragment ring [2]
    uint32_t afr[4][2][4];
    uint32_t bfr[2][8][2];

    // A loader: frag reg r of tile mt at step k8:
    //   k = k8*8 + tg + (r>=2 ? 4 : 0),  m = mt*16 + g + (r&1 ? 8 : 0)
    #define LOAD_A(buf, k8v) do {                                              \
        const float* _p = inW + (size_t)((k8v) * 8 + tg) * S_;                 \
        _Pragma("unroll")                                                      \
        for (int _mt = 0; _mt < 2; _mt++) {                                    \
            afr[buf][_mt][0] = __float_as_uint(_p[_mt * 16 + g]);              \
            afr[buf][_mt][1] = __float_as_uint(_p[_mt * 16 + g + 8]);          \
            afr[buf][_mt][2] = __float_as_uint(_p[4 * S_ + _mt * 16 + g]);     \
            afr[buf][_mt][3] = __float_as_uint(_p[4 * S_ + _mt * 16 + g + 8]); \
        }                                                                      \
    } while (0)

    #define LOAD_B(buf, k8v) do {                                              \
        const float2* _P = g_P + (size_t)(k8v) * 256 + lane;                   \
        _Pragma("unroll")                                                      \
        for (int _nt = 0; _nt < 8; _nt++) {                                    \
            float2 _v = _P[_nt * 32];                                          \
            bfr[buf][_nt][0] = __float_as_uint(_v.x);                          \
            bfr[buf][_nt][1] = __float_as_uint(_v.y);                          \
        }                                                                      \
    } while (0)

    // prologue: A for k8 = 0,1 ; B for k8 = 0
    LOAD_A(0, 0);
    LOAD_A(1, 1);
    LOAD_B(0, 0);

    #pragma unroll 4
    for (int k8 = 0; k8 < NK8; k8++) {
        // prefetch A at distance 2, B at distance 1 (clamped; redundant tail loads harmless)
        const int kA = (k8 + 2 < NK8) ? (k8 + 2) : (NK8 - 1);
        const int kB = (k8 + 1 < NK8) ? (k8 + 1) : (NK8 - 1);
        LOAD_A((k8 + 2) & 3, kA);
        LOAD_B((k8 + 1) & 1, kB);

        const int ca = k8 & 3;
        const int cb = k8 & 1;
        #pragma unroll
        for (int mt = 0; mt < 2; mt++)
            #pragma unroll
            for (int nt = 0; nt < 8; nt++)
                MMA_TF32(acc[mt][nt], afr[ca][mt], bfr[cb][nt]);
    }

    // ---- epilogue ----
    #pragma unroll
    for (int mt = 0; mt < 2; mt++) {
        #pragma unroll
        for (int nt = 0; nt < 8; nt++) {
            const int m0 = wid * 32 + mt * 16 + g;
            const int n0 = nt * 8 + tg * 2;
            float2 v01 = make_float2(acc[mt][nt][0], acc[mt][nt][1]);
            float2 v23 = make_float2(acc[mt][nt][2], acc[mt][nt][3]);
            *reinterpret_cast<float2*>(outB + (size_t)m0 * E_ + n0)       = v01;
            *reinterpret_cast<float2*>(outB + (size_t)(m0 + 8) * E_ + n0) = v23;
        }
    }
}

extern "C" void kernel_launch(void* const* d_in, const int* in_sizes, int n_in,
                              void* d_out, int out_size) {
    const float* in  = (const float*)d_in[0];   // [B, V, S] f32
    const float* emb = (const float*)d_in[1];   // [V, E]    f32
    float* out = (float*)d_out;                 // [B, S, E] f32

    embP_prep_kernel<<<256, 256>>>(emb);

    dim3 grid(S_ / 128, B_);   // 8 x 128 = 1024 CTAs
    Embedding_59476707115122_kernel<<<grid, 128>>>(in, out);
}